// round 2
// baseline (speedup 1.0000x reference)
#include <cuda_runtime.h>
#include <cstdint>

#define ATT_SCALE 0.125f
#define BB 2
#define LL 8192
#define SSS 4096
#define DD 1024
#define HH 16
#define HKVN 4
#define HDIM 64
#define NBLK 512          // L / 16
#define KVW 256           // HKV * HD

// ---------------- scratch (device globals, no allocation) ----------------
__device__ float g_pooled[BB * NBLK * DD];
__device__ float g_q[BB * NBLK * DD];
__device__ float g_k[BB * SSS * KVW];
__device__ float g_v[BB * SSS * KVW];
__device__ float g_ob[BB * NBLK * DD];

// ---------------- 1) block-mean pooling ----------------
__global__ void pool_kernel(const float* __restrict__ x, float* __restrict__ pooled) {
    int row = blockIdx.x;                      // b*512 + blk
    const float* base = x + (size_t)row * 16 * DD;
    float* outp = pooled + (size_t)row * DD;
#pragma unroll
    for (int j = 0; j < 4; j++) {
        int col = threadIdx.x + j * 256;
        float s = 0.f;
#pragma unroll
        for (int t = 0; t < 16; t++) s += base[t * DD + col];
        outp[col] = s * 0.0625f;
    }
}

// ---------------- tiled SGEMM (fp32, ping-pong double buffered) ----------------
// C[M,N] = A[M,K] @ B[K,N], all row-major. 256 threads, 16x16 layout, TMxTN/thread.
// BCAST: C row m is broadcast to 16 output token rows (out-projection epilogue).
template <int BM, int BN, int TM, int TN, bool BCAST>
__global__ void __launch_bounds__(256)
sgemm_kernel(const float* __restrict__ A, const float* __restrict__ B,
             float* __restrict__ C, int M, int N, int K) {
    constexpr int BK = 8;
    __shared__ float As[2][BK][BM];
    __shared__ float Bs[2][BK][BN];

    const int tid = threadIdx.x;
    const int tx = tid & 15, ty = tid >> 4;
    const int m0 = blockIdx.y * BM, n0 = blockIdx.x * BN;

    constexpr int RA = BM * BK / 256;
    constexpr int RB = BN * BK / 256;
    float ra[RA], rb[RB];

    float acc[TM][TN];
#pragma unroll
    for (int i = 0; i < TM; i++)
#pragma unroll
        for (int j = 0; j < TN; j++) acc[i][j] = 0.f;

    // initial tile -> buffer 0
#pragma unroll
    for (int i = 0; i < RA; i++) {
        int e = i * 256 + tid; int r = e >> 3; int c = e & 7;
        As[0][c][r] = A[(size_t)(m0 + r) * K + c];
    }
#pragma unroll
    for (int i = 0; i < RB; i++) {
        int e = i * 256 + tid; int r = e / BN; int c = e % BN;
        Bs[0][r][c] = B[(size_t)r * N + n0 + c];
    }
    __syncthreads();

    const int nt = K / BK;
    for (int t = 0; t < nt; t++) {
        const int cur = t & 1;
        if (t + 1 < nt) {
            const int k0 = (t + 1) * BK;
#pragma unroll
            for (int i = 0; i < RA; i++) {
                int e = i * 256 + tid; int r = e >> 3; int c = e & 7;
                ra[i] = A[(size_t)(m0 + r) * K + k0 + c];
            }
#pragma unroll
            for (int i = 0; i < RB; i++) {
                int e = i * 256 + tid; int r = e / BN; int c = e % BN;
                rb[i] = B[(size_t)(k0 + r) * N + n0 + c];
            }
        }
#pragma unroll
        for (int kk = 0; kk < BK; kk++) {
            float av[TM], bv[TN];
#pragma unroll
            for (int i = 0; i < TM; i++) av[i] = As[cur][kk][ty * TM + i];
#pragma unroll
            for (int j = 0; j < TN; j++) bv[j] = Bs[cur][kk][tx * TN + j];
#pragma unroll
            for (int i = 0; i < TM; i++)
#pragma unroll
                for (int j = 0; j < TN; j++) acc[i][j] += av[i] * bv[j];
        }
        if (t + 1 < nt) {
            const int nxt = cur ^ 1;
#pragma unroll
            for (int i = 0; i < RA; i++) {
                int e = i * 256 + tid; int r = e >> 3; int c = e & 7;
                As[nxt][c][r] = ra[i];
            }
#pragma unroll
            for (int i = 0; i < RB; i++) {
                int e = i * 256 + tid; int r = e / BN; int c = e % BN;
                Bs[nxt][r][c] = rb[i];
            }
        }
        __syncthreads();
    }

    if (!BCAST) {
#pragma unroll
        for (int i = 0; i < TM; i++) {
            int m = m0 + ty * TM + i;
#pragma unroll
            for (int j = 0; j < TN; j += 4) {
                float4 vv = make_float4(acc[i][j], acc[i][j + 1], acc[i][j + 2], acc[i][j + 3]);
                *(float4*)&C[(size_t)m * N + n0 + tx * TN + j] = vv;
            }
        }
    } else {
        // m -> (b = m>>9, blk = m&511); broadcast to 16 token rows
#pragma unroll
        for (int i = 0; i < TM; i++) {
            int m = m0 + ty * TM + i;
            int bo = (m >> 9) * LL + (m & 511) * 16;
#pragma unroll
            for (int j = 0; j < TN; j += 4) {
                float4 vv = make_float4(acc[i][j], acc[i][j + 1], acc[i][j + 2], acc[i][j + 3]);
                for (int tt = 0; tt < 16; tt++)
                    *(float4*)&C[(size_t)(bo + tt) * N + n0 + tx * TN + j] = vv;
            }
        }
    }
}

// ---------------- flash attention (fused, online softmax) ----------------
// grid: (nb/64, H, B). 64 query-blocks x 64-key chunks x HD=64.
// smem: Qt/Kt transposed [d][row] stride 68 for conflict-free float4 LDS.
#define TSTR 68
__global__ void __launch_bounds__(256)
attn_kernel(const float* __restrict__ q, const float* __restrict__ k,
            const float* __restrict__ v, const int* __restrict__ mask,
            float* __restrict__ ob) {
    extern __shared__ float sm[];
    float* Qt  = sm;                    // [64][68] transposed: Qt[d][r]
    float* Kt  = sm + 64 * TSTR;        // [64][68] transposed: Kt[d][c]
    float* Vs  = sm + 2 * 64 * TSTR;    // [64][68] row-major: Vs[kc][j]
    float* St  = sm + 3 * 64 * TSTR;    // [64][68] transposed: St[c][r]
    float* m_s = sm + 4 * 64 * TSTR;    // [64]
    float* l_s = m_s + 64;              // [64]
    float* a_s = l_s + 64;              // [64] per-chunk alpha
    int*  mskv = (int*)(a_s + 64);      // [64]

    const int tid = threadIdx.x;
    const int tx = tid & 15, ty = tid >> 4;
    const int blk0 = blockIdx.x * 64;
    const int h = blockIdx.y;
    const int b = blockIdx.z;
    const int g = h >> 2;               // kv group (hpg = 4)

    // load Q tile transposed: Qt[c][r] = q[(b*512+blk0+r), h*64+c]
#pragma unroll
    for (int i = 0; i < 4; i++) {
        int e = i * 256 + tid;
        int r = e >> 4, c4 = (e & 15) * 4;
        float4 qv = *(const float4*)&q[(size_t)(b * NBLK + blk0 + r) * DD + h * HDIM + c4];
        Qt[(c4 + 0) * TSTR + r] = qv.x;
        Qt[(c4 + 1) * TSTR + r] = qv.y;
        Qt[(c4 + 2) * TSTR + r] = qv.z;
        Qt[(c4 + 3) * TSTR + r] = qv.w;
    }
    if (tid < 64) { m_s[tid] = -3.0e38f; l_s[tid] = 0.f; }

    float o[4][4];
#pragma unroll
    for (int i = 0; i < 4; i++)
#pragma unroll
        for (int j = 0; j < 4; j++) o[i][j] = 0.f;

    for (int s0 = 0; s0 < SSS; s0 += 64) {
        __syncthreads();   // prev chunk's PV done; (first iter: orders Q/m/l writes)
        // load K chunk (transposed) + V chunk + mask
#pragma unroll
        for (int i = 0; i < 4; i++) {
            int e = i * 256 + tid;
            int r = e >> 4, c4 = (e & 15) * 4;
            size_t goff = (size_t)(b * SSS + s0 + r) * KVW + g * HDIM + c4;
            float4 kv = *(const float4*)&k[goff];
            Kt[(c4 + 0) * TSTR + r] = kv.x;
            Kt[(c4 + 1) * TSTR + r] = kv.y;
            Kt[(c4 + 2) * TSTR + r] = kv.z;
            Kt[(c4 + 3) * TSTR + r] = kv.w;
            float4 vv = *(const float4*)&v[goff];
            *(float4*)&Vs[r * TSTR + c4] = vv;
        }
        if (tid < 64) mskv[tid] = mask[b * SSS + s0 + tid];
        __syncthreads();

        // S = Q @ K^T  (4x4 per thread: rows ty*4.., cols tx*4..)
        float s[4][4];
#pragma unroll
        for (int i = 0; i < 4; i++)
#pragma unroll
            for (int j = 0; j < 4; j++) s[i][j] = 0.f;
#pragma unroll 8
        for (int kd = 0; kd < 64; kd++) {
            float4 aq = *(const float4*)&Qt[kd * TSTR + ty * 4];
            float4 bk = *(const float4*)&Kt[kd * TSTR + tx * 4];
            float av[4] = {aq.x, aq.y, aq.z, aq.w};
            float bv[4] = {bk.x, bk.y, bk.z, bk.w};
#pragma unroll
            for (int i = 0; i < 4; i++)
#pragma unroll
                for (int j = 0; j < 4; j++) s[i][j] += av[i] * bv[j];
        }
#pragma unroll
        for (int j = 0; j < 4; j++) {
            int c = tx * 4 + j;
            bool ok = mskv[c] != 0;
#pragma unroll
            for (int i = 0; i < 4; i++)
                St[c * TSTR + ty * 4 + i] = ok ? s[i][j] * ATT_SCALE : -3.4e38f;
        }
        __syncthreads();

        // online softmax: 4 threads per row; row = tid>>2, each scans 16 cols
        {
            int r = tid >> 2, sub = tid & 3;
            float mx = -3.4e38f;
#pragma unroll
            for (int cc = 0; cc < 16; cc++)
                mx = fmaxf(mx, St[(sub * 16 + cc) * TSTR + r]);
            mx = fmaxf(mx, __shfl_xor_sync(0xffffffffu, mx, 1));
            mx = fmaxf(mx, __shfl_xor_sync(0xffffffffu, mx, 2));
            float m_old = m_s[r];
            float m_new = fmaxf(m_old, mx);
            float psum = 0.f;
#pragma unroll
            for (int cc = 0; cc < 16; cc++) {
                int c = sub * 16 + cc;
                float arg = St[c * TSTR + r] - m_new;
                float p = __expf(fmaxf(arg, -80.f)) * (arg < -60.f ? 0.f : 1.f);
                St[c * TSTR + r] = p;
                psum += p;
            }
            psum += __shfl_xor_sync(0xffffffffu, psum, 1);
            psum += __shfl_xor_sync(0xffffffffu, psum, 2);
            if (sub == 0) {
                float al = __expf(fmaxf(m_old - m_new, -80.f)) * (m_old - m_new < -60.f ? 0.f : 1.f);
                a_s[r] = al;
                l_s[r] = l_s[r] * al + psum;
                m_s[r] = m_new;
            }
        }
        __syncthreads();

        // O = O*alpha + P @ V
        {
            float al[4];
#pragma unroll
            for (int i = 0; i < 4; i++) al[i] = a_s[ty * 4 + i];
#pragma unroll
            for (int i = 0; i < 4; i++)
#pragma unroll
                for (int j = 0; j < 4; j++) o[i][j] *= al[i];
#pragma unroll 8
            for (int kc = 0; kc < 64; kc++) {
                float4 pp = *(const float4*)&St[kc * TSTR + ty * 4];
                float4 vv = *(const float4*)&Vs[kc * TSTR + tx * 4];
                float pv[4] = {pp.x, pp.y, pp.z, pp.w};
                float vvv[4] = {vv.x, vv.y, vv.z, vv.w};
#pragma unroll
                for (int i = 0; i < 4; i++)
#pragma unroll
                    for (int j = 0; j < 4; j++) o[i][j] += pv[i] * vvv[j];
            }
        }
    }

    // finalize: divide by l, write to o_blocks [B*nb, H*HD]
#pragma unroll
    for (int i = 0; i < 4; i++) {
        int r = ty * 4 + i;
        float inv = 1.f / l_s[r];
        float4 vv = make_float4(o[i][0] * inv, o[i][1] * inv, o[i][2] * inv, o[i][3] * inv);
        *(float4*)&ob[(size_t)(b * NBLK + blk0 + r) * DD + h * HDIM + tx * 4] = vv;
    }
}

// ---------------- launcher ----------------
extern "C" void kernel_launch(void* const* d_in, const int* in_sizes, int n_in,
                              void* d_out, int out_size) {
    const float* x    = (const float*)d_in[0];
    const float* enc  = (const float*)d_in[1];
    const int*   mask = (const int*)d_in[2];
    const float* Wq   = (const float*)d_in[3];
    const float* Wk   = (const float*)d_in[4];
    const float* Wv   = (const float*)d_in[5];
    const float* Wo   = (const float*)d_in[6];
    float* out = (float*)d_out;

    float *pooled, *q, *k, *v, *ob;
    cudaGetSymbolAddress((void**)&pooled, g_pooled);
    cudaGetSymbolAddress((void**)&q, g_q);
    cudaGetSymbolAddress((void**)&k, g_k);
    cudaGetSymbolAddress((void**)&v, g_v);
    cudaGetSymbolAddress((void**)&ob, g_ob);

    // 1) pool decoder tokens into blocks
    pool_kernel<<<BB * NBLK, 256>>>(x, pooled);

    // 2) q projection: [1024,1024] @ [1024,1024] (64x64 tiles -> 256 blocks)
    sgemm_kernel<64, 64, 4, 4, false><<<dim3(DD / 64, BB * NBLK / 64), 256>>>(
        pooled, Wq, q, BB * NBLK, DD, DD);

    // 3) k,v projections: [8192,1024] @ [1024,256]
    sgemm_kernel<128, 128, 8, 8, false><<<dim3(KVW / 128, BB * SSS / 128), 256>>>(
        enc, Wk, k, BB * SSS, KVW, DD);
    sgemm_kernel<128, 128, 8, 8, false><<<dim3(KVW / 128, BB * SSS / 128), 256>>>(
        enc, Wv, v, BB * SSS, KVW, DD);

    // 4) fused flash attention
    int smem_bytes = (4 * 64 * TSTR + 3 * 64) * (int)sizeof(float) + 64 * (int)sizeof(int);
    cudaFuncSetAttribute(attn_kernel, cudaFuncAttributeMaxDynamicSharedMemorySize, smem_bytes);
    attn_kernel<<<dim3(NBLK / 64, HH, BB), 256, smem_bytes>>>(q, k, v, mask, ob);

    // 5) out projection fused with 16x token broadcast
    sgemm_kernel<64, 64, 4, 4, true><<<dim3(DD / 64, BB * NBLK / 64), 256>>>(
        ob, Wo, out, BB * NBLK, DD, DD);
}

// round 3
// speedup vs baseline: 2.8012x; 2.8012x over previous
#include <cuda_runtime.h>
#include <cuda_bf16.h>
#include <cstdint>

#define BB 2
#define SSS 4096
#define DD 1024
#define NBLK 512
#define KVW 256

typedef __nv_bfloat16 bf16;

// ---------------- scratch (device globals, no allocation) ----------------
__device__ float g_pooled[BB * NBLK * DD];
__device__ bf16 g_q_hi[BB * NBLK * DD], g_q_lo[BB * NBLK * DD];
__device__ bf16 g_k_hi[BB * SSS * KVW], g_k_lo[BB * SSS * KVW];
__device__ bf16 g_v_hi[BB * SSS * KVW], g_v_lo[BB * SSS * KVW];
__device__ bf16 g_vt_hi[BB * SSS * KVW], g_vt_lo[BB * SSS * KVW];
__device__ float g_ob[BB * NBLK * DD];

// ---------------- helpers ----------------
__device__ __forceinline__ uint32_t sptr(const void* p) {
    return (uint32_t)__cvta_generic_to_shared(p);
}
#define CP16(dst, src) asm volatile("cp.async.cg.shared.global [%0],[%1],16;\n" ::"r"(dst), "l"(src))
#define CPCOMMIT() asm volatile("cp.async.commit_group;\n")
#define CPWAIT0() asm volatile("cp.async.wait_group 0;\n")
#define CPWAIT1() asm volatile("cp.async.wait_group 1;\n")

__device__ __forceinline__ void split2(float x, float y, uint32_t& h, uint32_t& l) {
    bf16 hx = __float2bfloat16_rn(x), hy = __float2bfloat16_rn(y);
    float rx = x - __bfloat162float(hx), ry = y - __bfloat162float(hy);
    bf16 lx = __float2bfloat16_rn(rx), ly = __float2bfloat16_rn(ry);
    h = ((uint32_t)__bfloat16_as_ushort(hy) << 16) | __bfloat16_as_ushort(hx);
    l = ((uint32_t)__bfloat16_as_ushort(ly) << 16) | __bfloat16_as_ushort(lx);
}

__device__ __forceinline__ void mma_bf(float* c, const uint32_t* a, const uint32_t* b) {
    asm volatile(
        "mma.sync.aligned.m16n8k16.row.col.f32.bf16.bf16.f32 "
        "{%0,%1,%2,%3},{%4,%5,%6,%7},{%8,%9},{%0,%1,%2,%3};"
        : "+f"(c[0]), "+f"(c[1]), "+f"(c[2]), "+f"(c[3])
        : "r"(a[0]), "r"(a[1]), "r"(a[2]), "r"(a[3]), "r"(b[0]), "r"(b[1]));
}
__device__ __forceinline__ void mma3(float* c, const uint32_t* ah, const uint32_t* al,
                                     const uint32_t* bh, const uint32_t* bl) {
    mma_bf(c, ah, bh);
    mma_bf(c, ah, bl);
    mma_bf(c, al, bh);
}

// ---------------- 1) block-mean pooling ----------------
__global__ void pool_kernel(const float* __restrict__ x, float* __restrict__ pooled) {
    int row = blockIdx.x;
    const float* base = x + (size_t)row * 16 * DD;
    float* outp = pooled + (size_t)row * DD;
#pragma unroll
    for (int j = 0; j < 4; j++) {
        int col = threadIdx.x + j * 256;
        float s = 0.f;
#pragma unroll
        for (int t = 0; t < 16; t++) s += base[t * DD + col];
        outp[col] = s * 0.0625f;
    }
}

// ---------------- bf16x3 tensor-core GEMM ----------------
// C[M,N] = A[M,K=1024] @ B[K,N]; BN=128 fixed; 8 warps as 2x4, warp tile (BM/2)x32.
// EPI 0: write hi/lo bf16 planes (*scale). EPI 1: fp32 + 16x token broadcast.
template <int BM, int EPI>
__global__ void __launch_bounds__(256) gemm3(
    const float* __restrict__ A, const float* __restrict__ Bm,
    bf16* __restrict__ Chi, bf16* __restrict__ Clo, float* __restrict__ Cf,
    int M, int N, float scale) {
    constexpr int K = 1024;
    constexpr int MF = BM / 32;   // m-frags per warp
    constexpr int RA = BM / 32;   // float4 per thread for A tile
    extern __shared__ bf16 sm[];
    bf16* As = sm;                 // [2buf][2pl][BM][40]
    bf16* Bs = sm + 2 * 2 * BM * 40;  // [2buf][2pl][128][40]

    const int tid = threadIdx.x;
    const int w = tid >> 5, lane = tid & 31, g = lane >> 2, t4 = lane & 3;
    const int m0 = blockIdx.y * BM, n0 = blockIdx.x * 128;
    const int wm = (w >> 2) * (BM / 2), wn = (w & 3) * 32;
    const int bn = tid & 127, bq = tid >> 7;

    float acc[MF][4][4];
#pragma unroll
    for (int i = 0; i < MF; i++)
#pragma unroll
        for (int j = 0; j < 4; j++)
#pragma unroll
            for (int e = 0; e < 4; e++) acc[i][j][e] = 0.f;

    float4 ra[RA];
    float rb[16];

    auto gload = [&](int kt) {
#pragma unroll
        for (int i = 0; i < RA; i++) {
            int idx = i * 256 + tid, r = idx >> 3, kq = idx & 7;
            ra[i] = *reinterpret_cast<const float4*>(&A[(size_t)(m0 + r) * K + kt * 32 + kq * 4]);
        }
#pragma unroll
        for (int i = 0; i < 4; i++) {
            int q = bq * 4 + i;
#pragma unroll
            for (int j = 0; j < 4; j++)
                rb[i * 4 + j] = Bm[(size_t)(kt * 32 + q * 4 + j) * N + n0 + bn];
        }
    };
    auto sstore = [&](int buf) {
#pragma unroll
        for (int i = 0; i < RA; i++) {
            int idx = i * 256 + tid, r = idx >> 3, kq = idx & 7;
            uint32_t h0, l0, h1, l1;
            split2(ra[i].x, ra[i].y, h0, l0);
            split2(ra[i].z, ra[i].w, h1, l1);
            uint32_t* ph = (uint32_t*)(As + ((buf * 2 + 0) * BM + r) * 40);
            uint32_t* pl = (uint32_t*)(As + ((buf * 2 + 1) * BM + r) * 40);
            *(uint2*)&ph[kq * 2] = make_uint2(h0, h1);
            *(uint2*)&pl[kq * 2] = make_uint2(l0, l1);
        }
#pragma unroll
        for (int i = 0; i < 4; i++) {
            int q = bq * 4 + i;
            uint32_t h0, l0, h1, l1;
            split2(rb[i * 4 + 0], rb[i * 4 + 1], h0, l0);
            split2(rb[i * 4 + 2], rb[i * 4 + 3], h1, l1);
            uint32_t* ph = (uint32_t*)(Bs + ((buf * 2 + 0) * 128 + bn) * 40);
            uint32_t* pl = (uint32_t*)(Bs + ((buf * 2 + 1) * 128 + bn) * 40);
            *(uint2*)&ph[q * 2] = make_uint2(h0, h1);
            *(uint2*)&pl[q * 2] = make_uint2(l0, l1);
        }
    };
    auto compute = [&](int buf) {
        const uint32_t* Ah = (const uint32_t*)(As + (buf * 2 + 0) * BM * 40);
        const uint32_t* Al = (const uint32_t*)(As + (buf * 2 + 1) * BM * 40);
        const uint32_t* Bh = (const uint32_t*)(Bs + (buf * 2 + 0) * 128 * 40);
        const uint32_t* Bl = (const uint32_t*)(Bs + (buf * 2 + 1) * 128 * 40);
#pragma unroll
        for (int ks = 0; ks < 2; ks++) {
            uint32_t ah[MF][4], al[MF][4];
#pragma unroll
            for (int mf = 0; mf < MF; mf++) {
                int r0 = (wm + mf * 16 + g) * 20 + ks * 8 + t4;
                int r1 = (wm + mf * 16 + g + 8) * 20 + ks * 8 + t4;
                ah[mf][0] = Ah[r0]; ah[mf][1] = Ah[r1];
                ah[mf][2] = Ah[r0 + 4]; ah[mf][3] = Ah[r1 + 4];
                al[mf][0] = Al[r0]; al[mf][1] = Al[r1];
                al[mf][2] = Al[r0 + 4]; al[mf][3] = Al[r1 + 4];
            }
#pragma unroll
            for (int nf = 0; nf < 4; nf++) {
                int nr = (wn + nf * 8 + g) * 20 + ks * 8 + t4;
                uint32_t bh[2] = {Bh[nr], Bh[nr + 4]};
                uint32_t bl[2] = {Bl[nr], Bl[nr + 4]};
#pragma unroll
                for (int mf = 0; mf < MF; mf++) mma3(acc[mf][nf], ah[mf], al[mf], bh, bl);
            }
        }
    };

    gload(0);
    sstore(0);
    __syncthreads();
    for (int t = 0; t < 32; t++) {
        int cur = t & 1;
        if (t < 31) gload(t + 1);
        compute(cur);
        if (t < 31) sstore(cur ^ 1);
        __syncthreads();
    }

#pragma unroll
    for (int mf = 0; mf < MF; mf++) {
#pragma unroll
        for (int nf = 0; nf < 4; nf++) {
            int nc = n0 + wn + nf * 8 + 2 * t4;
#pragma unroll
            for (int hh = 0; hh < 2; hh++) {
                int m = m0 + wm + mf * 16 + g + hh * 8;
                float x0 = acc[mf][nf][hh * 2] * scale;
                float x1 = acc[mf][nf][hh * 2 + 1] * scale;
                if (EPI == 0) {
                    uint32_t hw, lw;
                    split2(x0, x1, hw, lw);
                    *reinterpret_cast<uint32_t*>(&Chi[(size_t)m * N + nc]) = hw;
                    *reinterpret_cast<uint32_t*>(&Clo[(size_t)m * N + nc]) = lw;
                } else {
                    int b = m >> 9, blk = m & 511;
                    size_t base = ((size_t)b * 8192 + blk * 16) * 1024 + nc;
                    float2 v = make_float2(x0, x1);
#pragma unroll
                    for (int tt = 0; tt < 16; tt++)
                        *reinterpret_cast<float2*>(&Cf[base + (size_t)tt * 1024]) = v;
                }
            }
        }
    }
}

// ---------------- V transpose: [b*S][256] -> [b*256 + d][S] (both planes) ----------------
__global__ void transpose_v(const bf16* __restrict__ vh, const bf16* __restrict__ vl,
                            bf16* __restrict__ th, bf16* __restrict__ tl) {
    __shared__ bf16 sh[32][33], sl[32][33];
    int s0 = blockIdx.x * 32, d0 = blockIdx.y * 32, b = blockIdx.z;
    int x = threadIdx.x, y = threadIdx.y;
#pragma unroll
    for (int i = 0; i < 32; i += 8) {
        size_t src = (size_t)(b * SSS + s0 + y + i) * KVW + d0 + x;
        sh[y + i][x] = vh[src];
        sl[y + i][x] = vl[src];
    }
    __syncthreads();
#pragma unroll
    for (int i = 0; i < 32; i += 8) {
        size_t dst = (size_t)(b * KVW + d0 + y + i) * SSS + s0 + x;
        th[dst] = sh[x][y + i];
        tl[dst] = sl[x][y + i];
    }
}

// ---------------- fused flash attention (bf16x3 mma, online softmax) ----------------
// grid (4, 16, 2): 128 q-rows per block, 8 warps x 16 rows; 64-key chunks, cp.async x2.
__global__ void __launch_bounds__(256) attn3(
    const bf16* __restrict__ qhi, const bf16* __restrict__ qlo,
    const bf16* __restrict__ khi, const bf16* __restrict__ klo,
    const bf16* __restrict__ vthi, const bf16* __restrict__ vtlo,
    const int* __restrict__ mask, float* __restrict__ ob) {
    extern __shared__ bf16 sm[];
    bf16* Qs = sm;                       // [2pl][128][72]
    bf16* Ks = sm + 2 * 128 * 72;        // [2buf][2pl][64][72]
    bf16* Vts = Ks + 4 * 64 * 72;        // [2buf][2pl][64][72]
    int* msk = (int*)(Vts + 4 * 64 * 72);  // [2][64]

    const int tid = threadIdx.x;
    const int w = tid >> 5, lane = tid & 31, g = lane >> 2, t4 = lane & 3;
    const int blk0 = blockIdx.x * 128, h = blockIdx.y, b = blockIdx.z, kg = h >> 2;

    // Q tile (both planes), part of cp.async group 0
#pragma unroll
    for (int pl = 0; pl < 2; pl++) {
        const bf16* src = pl ? qlo : qhi;
#pragma unroll
        for (int i = 0; i < 4; i++) {
            int idx = i * 256 + tid, r = idx >> 3, sg = idx & 7;
            CP16(sptr(Qs + (pl * 128 + r) * 72 + sg * 8),
                 src + (size_t)(b * NBLK + blk0 + r) * DD + h * 64 + sg * 8);
        }
    }
    auto loadchunk = [&](int buf, int c) {
        int s0 = c * 64;
#pragma unroll
        for (int pl = 0; pl < 2; pl++) {
            const bf16* ksrc = pl ? klo : khi;
            const bf16* vsrc = pl ? vtlo : vthi;
#pragma unroll
            for (int i = 0; i < 2; i++) {
                int idx = i * 256 + tid, r = idx >> 3, sg = idx & 7;
                CP16(sptr(Ks + ((buf * 2 + pl) * 64 + r) * 72 + sg * 8),
                     ksrc + (size_t)(b * SSS + s0 + r) * KVW + kg * 64 + sg * 8);
                CP16(sptr(Vts + ((buf * 2 + pl) * 64 + r) * 72 + sg * 8),
                     vsrc + (size_t)((b * 4 + kg) * 64 + r) * SSS + s0 + sg * 8);
            }
        }
        if (tid < 16) CP16(sptr(msk + buf * 64 + tid * 4), mask + b * SSS + s0 + tid * 4);
    };
    loadchunk(0, 0);
    CPCOMMIT();

    float o[8][4];
#pragma unroll
    for (int i = 0; i < 8; i++)
#pragma unroll
        for (int j = 0; j < 4; j++) o[i][j] = 0.f;
    float m0v = -1e30f, m1v = -1e30f, l0v = 0.f, l1v = 0.f;

    for (int c = 0; c < 64; c++) {
        int buf = c & 1;
        if (c < 63) {
            loadchunk(buf ^ 1, c + 1);
            CPCOMMIT();
            CPWAIT1();
        } else {
            CPWAIT0();
        }
        __syncthreads();

        const uint32_t* Qh = (const uint32_t*)Qs;
        const uint32_t* Ql = (const uint32_t*)(Qs + 128 * 72);
        const uint32_t* Kh = (const uint32_t*)(Ks + (buf * 2 + 0) * 64 * 72);
        const uint32_t* Kl = (const uint32_t*)(Ks + (buf * 2 + 1) * 64 * 72);
        const uint32_t* Vh = (const uint32_t*)(Vts + (buf * 2 + 0) * 64 * 72);
        const uint32_t* Vl = (const uint32_t*)(Vts + (buf * 2 + 1) * 64 * 72);

        float sc[8][4];
#pragma unroll
        for (int i = 0; i < 8; i++)
#pragma unroll
            for (int j = 0; j < 4; j++) sc[i][j] = 0.f;

        // S = Q @ K^T
#pragma unroll
        for (int ks = 0; ks < 4; ks++) {
            int r0 = (w * 16 + g) * 36 + ks * 8 + t4;
            int r1 = (w * 16 + g + 8) * 36 + ks * 8 + t4;
            uint32_t ah[4] = {Qh[r0], Qh[r1], Qh[r0 + 4], Qh[r1 + 4]};
            uint32_t al[4] = {Ql[r0], Ql[r1], Ql[r0 + 4], Ql[r1 + 4]};
#pragma unroll
            for (int nf = 0; nf < 8; nf++) {
                int kr = (nf * 8 + g) * 36 + ks * 8 + t4;
                uint32_t bh[2] = {Kh[kr], Kh[kr + 4]};
                uint32_t bl[2] = {Kl[kr], Kl[kr + 4]};
                mma3(sc[nf], ah, al, bh, bl);
            }
        }
        // mask + row max
        float rm0 = -1e30f, rm1 = -1e30f;
#pragma unroll
        for (int nf = 0; nf < 8; nf++) {
            int c0i = nf * 8 + 2 * t4;
            int mv0 = msk[buf * 64 + c0i], mv1 = msk[buf * 64 + c0i + 1];
            sc[nf][0] = mv0 ? sc[nf][0] : -1e30f;
            sc[nf][1] = mv1 ? sc[nf][1] : -1e30f;
            sc[nf][2] = mv0 ? sc[nf][2] : -1e30f;
            sc[nf][3] = mv1 ? sc[nf][3] : -1e30f;
            rm0 = fmaxf(rm0, fmaxf(sc[nf][0], sc[nf][1]));
            rm1 = fmaxf(rm1, fmaxf(sc[nf][2], sc[nf][3]));
        }
        rm0 = fmaxf(rm0, __shfl_xor_sync(~0u, rm0, 1));
        rm0 = fmaxf(rm0, __shfl_xor_sync(~0u, rm0, 2));
        rm1 = fmaxf(rm1, __shfl_xor_sync(~0u, rm1, 1));
        rm1 = fmaxf(rm1, __shfl_xor_sync(~0u, rm1, 2));
        float mn0 = fmaxf(m0v, rm0), mn1 = fmaxf(m1v, rm1);
        float al0 = __expf(m0v - mn0), al1 = __expf(m1v - mn1);
        float ps0 = 0.f, ps1 = 0.f;
#pragma unroll
        for (int nf = 0; nf < 8; nf++) {
            sc[nf][0] = __expf(sc[nf][0] - mn0);
            sc[nf][1] = __expf(sc[nf][1] - mn0);
            sc[nf][2] = __expf(sc[nf][2] - mn1);
            sc[nf][3] = __expf(sc[nf][3] - mn1);
            ps0 += sc[nf][0] + sc[nf][1];
            ps1 += sc[nf][2] + sc[nf][3];
        }
        ps0 += __shfl_xor_sync(~0u, ps0, 1);
        ps0 += __shfl_xor_sync(~0u, ps0, 2);
        ps1 += __shfl_xor_sync(~0u, ps1, 1);
        ps1 += __shfl_xor_sync(~0u, ps1, 2);
        l0v = l0v * al0 + ps0;
        l1v = l1v * al1 + ps1;
        m0v = mn0;
        m1v = mn1;
#pragma unroll
        for (int nf = 0; nf < 8; nf++) {
            o[nf][0] *= al0; o[nf][1] *= al0;
            o[nf][2] *= al1; o[nf][3] *= al1;
        }
        // O += P @ V  (P's C-frag layout == A-frag layout; split hi/lo on the fly)
#pragma unroll
        for (int kc = 0; kc < 4; kc++) {
            uint32_t ah[4], al4[4];
            split2(sc[2 * kc][0], sc[2 * kc][1], ah[0], al4[0]);
            split2(sc[2 * kc][2], sc[2 * kc][3], ah[1], al4[1]);
            split2(sc[2 * kc + 1][0], sc[2 * kc + 1][1], ah[2], al4[2]);
            split2(sc[2 * kc + 1][2], sc[2 * kc + 1][3], ah[3], al4[3]);
#pragma unroll
            for (int nf = 0; nf < 8; nf++) {
                int vr = (nf * 8 + g) * 36 + kc * 8 + t4;
                uint32_t bh[2] = {Vh[vr], Vh[vr + 4]};
                uint32_t bl[2] = {Vl[vr], Vl[vr + 4]};
                mma3(o[nf], ah, al4, bh, bl);
            }
        }
        __syncthreads();
    }

    float i0 = 1.f / l0v, i1 = 1.f / l1v;
#pragma unroll
    for (int nf = 0; nf < 8; nf++) {
        int col = h * 64 + nf * 8 + 2 * t4;
        size_t r0 = (size_t)(b * NBLK + blk0 + w * 16 + g) * DD + col;
        *reinterpret_cast<float2*>(&ob[r0]) = make_float2(o[nf][0] * i0, o[nf][1] * i0);
        *reinterpret_cast<float2*>(&ob[r0 + 8 * DD]) = make_float2(o[nf][2] * i1, o[nf][3] * i1);
    }
}

// ---------------- launcher ----------------
extern "C" void kernel_launch(void* const* d_in, const int* in_sizes, int n_in,
                              void* d_out, int out_size) {
    const float* x = (const float*)d_in[0];
    const float* enc = (const float*)d_in[1];
    const int* mask = (const int*)d_in[2];
    const float* Wq = (const float*)d_in[3];
    const float* Wk = (const float*)d_in[4];
    const float* Wv = (const float*)d_in[5];
    const float* Wo = (const float*)d_in[6];
    float* out = (float*)d_out;

    float *pooled, *ob;
    bf16 *qhi, *qlo, *khi, *klo, *vhi, *vlo, *vthi, *vtlo;
    cudaGetSymbolAddress((void**)&pooled, g_pooled);
    cudaGetSymbolAddress((void**)&ob, g_ob);
    cudaGetSymbolAddress((void**)&qhi, g_q_hi);
    cudaGetSymbolAddress((void**)&qlo, g_q_lo);
    cudaGetSymbolAddress((void**)&khi, g_k_hi);
    cudaGetSymbolAddress((void**)&klo, g_k_lo);
    cudaGetSymbolAddress((void**)&vhi, g_v_hi);
    cudaGetSymbolAddress((void**)&vlo, g_v_lo);
    cudaGetSymbolAddress((void**)&vthi, g_vt_hi);
    cudaGetSymbolAddress((void**)&vtlo, g_vt_lo);

    const int smem_g128 = (2 * 2 * 128 * 40 + 2 * 2 * 128 * 40) * 2;  // 81920
    const int smem_g64 = (2 * 2 * 64 * 40 + 2 * 2 * 128 * 40) * 2;    // 61440
    const int smem_a = (2 * 128 * 72 + 4 * 64 * 72 + 4 * 64 * 72) * 2 + 2 * 64 * 4;  // 111104
    cudaFuncSetAttribute(gemm3<64, 0>, cudaFuncAttributeMaxDynamicSharedMemorySize, smem_g64);
    cudaFuncSetAttribute(gemm3<64, 1>, cudaFuncAttributeMaxDynamicSharedMemorySize, smem_g64);
    cudaFuncSetAttribute(gemm3<128, 0>, cudaFuncAttributeMaxDynamicSharedMemorySize, smem_g128);
    cudaFuncSetAttribute(attn3, cudaFuncAttributeMaxDynamicSharedMemorySize, smem_a);

    // 1) pool
    pool_kernel<<<BB * NBLK, 256>>>(x, pooled);
    // 2) Q projection (scale folded in)
    gemm3<64, 0><<<dim3(8, 16), 256, smem_g64>>>(pooled, Wq, qhi, qlo, nullptr, 1024, 1024, 0.125f);
    // 3) K, V projections
    gemm3<128, 0><<<dim3(2, 64), 256, smem_g128>>>(enc, Wk, khi, klo, nullptr, BB * SSS, KVW, 1.f);
    gemm3<128, 0><<<dim3(2, 64), 256, smem_g128>>>(enc, Wv, vhi, vlo, nullptr, BB * SSS, KVW, 1.f);
    // 4) V transpose for PV fragment layout
    transpose_v<<<dim3(SSS / 32, KVW / 32, BB), dim3(32, 8)>>>(vhi, vlo, vthi, vtlo);
    // 5) fused flash attention
    attn3<<<dim3(4, 16, 2), 256, smem_a>>>(qhi, qlo, khi, klo, vthi, vtlo, mask, ob);
    // 6) out projection + 16x token broadcast
    gemm3<64, 1><<<dim3(8, 16), 256, smem_g64>>>(ob, Wo, nullptr, nullptr, out, 1024, 1024, 1.f);
}